// round 1
// baseline (speedup 1.0000x reference)
#include <cuda_runtime.h>
#include <math.h>

#define NB   32
#define D    128
#define L    2048
#define WIN  63          // half-window: |i-j| <= 63
#define WSZ  127         // window size
#define TI   32          // i-tile for banded kernel
#define JROWS (TI + 2*WIN)   // 158

// ---------------- scratch (device globals; no allocation) ----------------
__device__ float g_sq [NB*L*D];   // sigmoid(q)
__device__ float g_ek [NB*L*D];   // exp(k)
__device__ float g_ekv[NB*L*D];   // first v, then exp(k)*v (in-place in k_sums)
__device__ float g_y  [NB*L*D];   // y before out-proj
__device__ float g_w  [L*WSZ];    // exp(pos_bias)-1 on the band (0 off-edge)
__device__ float g_partN[16*NB*D];
__device__ float g_partD[16*NB*D];
__device__ float g_Snum[NB*D];
__device__ float g_Sden[NB*D];

// ---------------- K0: band weights ----------------
__global__ void k_window(const float* __restrict__ pos_bias) {
    int i  = blockIdx.x;
    int jo = threadIdx.x;
    if (jo < WSZ) {
        int j = i - WIN + jo;
        float val = 0.f;
        if (j >= 0 && j < L) val = expf(pos_bias[(size_t)i * L + j]) - 1.f;
        g_w[i * WSZ + jo] = val;
    }
}

// ---------------- K1: QKV projection (+ elementwise transforms) ----------
// grid (3 proj, 32 l-tiles, NB), 256 threads, dyn smem = 96KB
__global__ void k_qkv(const float* __restrict__ x,
                      const float* __restrict__ Wq, const float* __restrict__ bq,
                      const float* __restrict__ Wk, const float* __restrict__ bk,
                      const float* __restrict__ Wv, const float* __restrict__ bv) {
    extern __shared__ float sm[];
    float* xs = sm;            // [128 c][64 l]
    float* ws = sm + 128 * 64; // [128 c][128 d]
    const int proj  = blockIdx.x;
    const int lbase = blockIdx.y * 64;
    const int n     = blockIdx.z;
    const float* Wm = (proj == 0) ? Wq : (proj == 1) ? Wk : Wv;
    const float* bm = (proj == 0) ? bq : (proj == 1) ? bk : bv;
    const int tid = threadIdx.x;

    // x tile transposed into smem: xs[c*64 + l] = x[n, c, lbase+l]
    for (int idx = tid; idx < 128 * 64; idx += 256) {
        int c = idx >> 6, l = idx & 63;
        xs[idx] = x[(size_t)n * D * L + (size_t)c * L + lbase + l];
    }
    for (int idx = tid * 4; idx < 128 * 128; idx += 256 * 4)
        *(float4*)&ws[idx] = *(const float4*)&Wm[idx];
    __syncthreads();

    const int dq = (tid & 31) * 4;   // 4 consecutive d
    const int l0 = (tid >> 5) * 8;   // 8 consecutive l
    float acc[8][4];
    #pragma unroll
    for (int a = 0; a < 8; a++)
        #pragma unroll
        for (int b = 0; b < 4; b++) acc[a][b] = 0.f;

    for (int c = 0; c < 128; c++) {
        float4 wv = *(float4*)&ws[c * 128 + dq];
        float4 xa = *(float4*)&xs[c * 64 + l0];
        float4 xb = *(float4*)&xs[c * 64 + l0 + 4];
        float xv[8] = {xa.x, xa.y, xa.z, xa.w, xb.x, xb.y, xb.z, xb.w};
        #pragma unroll
        for (int a = 0; a < 8; a++) {
            acc[a][0] += xv[a] * wv.x;
            acc[a][1] += xv[a] * wv.y;
            acc[a][2] += xv[a] * wv.z;
            acc[a][3] += xv[a] * wv.w;
        }
    }

    float4 bb = *(const float4*)&bm[dq];
    size_t obase = (size_t)n * L * D + (size_t)(lbase + l0) * D + dq;
    #pragma unroll
    for (int a = 0; a < 8; a++) {
        float r0 = acc[a][0] + bb.x, r1 = acc[a][1] + bb.y;
        float r2 = acc[a][2] + bb.z, r3 = acc[a][3] + bb.w;
        float4 o;
        if (proj == 0) {            // sigmoid(q)
            o.x = 1.f / (1.f + expf(-r0));
            o.y = 1.f / (1.f + expf(-r1));
            o.z = 1.f / (1.f + expf(-r2));
            o.w = 1.f / (1.f + expf(-r3));
            *(float4*)&g_sq[obase + (size_t)a * D] = o;
        } else if (proj == 1) {     // exp(k)
            o.x = expf(r0); o.y = expf(r1); o.z = expf(r2); o.w = expf(r3);
            *(float4*)&g_ek[obase + (size_t)a * D] = o;
        } else {                    // raw v
            o.x = r0; o.y = r1; o.z = r2; o.w = r3;
            *(float4*)&g_ekv[obase + (size_t)a * D] = o;
        }
    }
}

// ---------------- K2: partial column sums; ekv = ek*v in place ----------
// grid (NB, 16), 128 threads
__global__ void k_sums() {
    const int n = blockIdx.x, chunk = blockIdx.y, d = threadIdx.x;
    float sn = 0.f, sd = 0.f;
    size_t base = (size_t)n * L * D + d;
    const int l0 = chunk * 128;
    for (int l = l0; l < l0 + 128; l++) {
        size_t off = base + (size_t)l * D;
        float e  = g_ek[off];
        float v  = g_ekv[off];
        float ev = e * v;
        g_ekv[off] = ev;
        sn += ev; sd += e;
    }
    g_partN[(chunk * NB + n) * D + d] = sn;
    g_partD[(chunk * NB + n) * D + d] = sd;
}

// grid (NB), 128 threads — deterministic reduction over 16 chunks
__global__ void k_red() {
    const int n = blockIdx.x, d = threadIdx.x;
    float sn = 0.f, sd = 0.f;
    for (int c = 0; c < 16; c++) {
        sn += g_partN[(c * NB + n) * D + d];
        sd += g_partD[(c * NB + n) * D + d];
    }
    g_Snum[n * D + d] = sn;
    g_Sden[n * D + d] = sd;
}

// ---------------- K3: banded AFT pass -> y ----------------
// grid (L/TI, NB), 256 threads, dyn smem = (2*JROWS*128 + TI*WSZ)*4 = 178048 B
__global__ void k_aft() {
    extern __shared__ float sm[];
    float* eks  = sm;                    // [JROWS][128]
    float* ekvs = sm + JROWS * 128;      // [JROWS][128]
    float* wss  = sm + 2 * JROWS * 128;  // [TI][WSZ]
    const int n     = blockIdx.y;
    const int ibase = blockIdx.x * TI;
    const int tid   = threadIdx.x;
    const int jlo   = ibase - WIN;

    for (int idx = tid; idx < JROWS * 128; idx += 256) {
        int r = idx >> 7, d = idx & 127;
        int j = jlo + r;
        float e = 0.f, ev = 0.f;
        if (j >= 0 && j < L) {
            size_t off = (size_t)n * L * D + (size_t)j * D + d;
            e  = g_ek[off];
            ev = g_ekv[off];
        }
        eks[idx] = e; ekvs[idx] = ev;
    }
    for (int idx = tid; idx < TI * WSZ; idx += 256) {
        int il = idx / WSZ, jo = idx % WSZ;
        wss[idx] = g_w[(size_t)(ibase + il) * WSZ + jo];
    }
    __syncthreads();

    const int dq = (tid & 31) * 4;
    const int ig = tid >> 5;   // 0..7
    #pragma unroll
    for (int rep = 0; rep < 4; rep++) {
        const int il = ig + rep * 8;      // i within tile
        const int i  = ibase + il;
        float4 num = *(float4*)&g_Snum[n * D + dq];
        float4 den = *(float4*)&g_Sden[n * D + dq];
        const float* er  = &eks [il * 128 + dq];   // row il+jo holds j = i-63+jo
        const float* evr = &ekvs[il * 128 + dq];
        const float* wr  = &wss [il * WSZ];
        #pragma unroll 4
        for (int jo = 0; jo < WSZ; jo++) {
            float  wv  = wr[jo];
            float4 e4  = *(float4*)&er [jo * 128];
            float4 ev4 = *(float4*)&evr[jo * 128];
            num.x += wv * ev4.x; num.y += wv * ev4.y;
            num.z += wv * ev4.z; num.w += wv * ev4.w;
            den.x += wv * e4.x;  den.y += wv * e4.y;
            den.z += wv * e4.z;  den.w += wv * e4.w;
        }
        size_t qoff = (size_t)n * L * D + (size_t)i * D + dq;
        float4 sq = *(float4*)&g_sq[qoff];
        float4 y;
        y.x = sq.x * num.x / den.x;
        y.y = sq.y * num.y / den.y;
        y.z = sq.z * num.z / den.z;
        y.w = sq.w * num.w / den.w;
        *(float4*)&g_y[qoff] = y;
    }
}

// ---------------- K4: output projection + transpose to [N,C,L] ----------
// grid (32 l-tiles, NB), 256 threads, dyn smem = 96KB
__global__ void k_out(const float* __restrict__ Wo, const float* __restrict__ bo,
                      float* __restrict__ out) {
    extern __shared__ float sm[];
    float* ys = sm;            // [64 l][128 d]
    float* ws = sm + 64 * 128; // [128 d][128 c]
    const int lbase = blockIdx.x * 64;
    const int n     = blockIdx.y;
    const int tid   = threadIdx.x;

    for (int idx = tid; idx < 64 * 128; idx += 256) {
        int l = idx >> 7, d = idx & 127;
        ys[idx] = g_y[(size_t)n * L * D + (size_t)(lbase + l) * D + d];
    }
    for (int idx = tid * 4; idx < 128 * 128; idx += 256 * 4)
        *(float4*)&ws[idx] = *(const float4*)&Wo[idx];
    __syncthreads();

    const int cq = (tid & 31) * 4;
    const int l0 = (tid >> 5) * 8;
    float acc[8][4];
    #pragma unroll
    for (int a = 0; a < 8; a++)
        #pragma unroll
        for (int b = 0; b < 4; b++) acc[a][b] = 0.f;

    for (int d = 0; d < 128; d++) {
        float4 wv = *(float4*)&ws[d * 128 + cq];   // Wo[d][cq..cq+3]
        #pragma unroll
        for (int a = 0; a < 8; a++) {
            float yv = ys[(l0 + a) * 128 + d];
            acc[a][0] += yv * wv.x;
            acc[a][1] += yv * wv.y;
            acc[a][2] += yv * wv.z;
            acc[a][3] += yv * wv.w;
        }
    }

    float4 bb = *(const float4*)&bo[cq];
    float bia[4] = {bb.x, bb.y, bb.z, bb.w};
    #pragma unroll
    for (int b = 0; b < 4; b++) {
        size_t obase = (size_t)n * D * L + (size_t)(cq + b) * L + lbase + l0;
        #pragma unroll
        for (int a = 0; a < 8; a++)
            out[obase + a] = acc[a][b] + bia[b];
    }
}

// ---------------- launch ----------------
extern "C" void kernel_launch(void* const* d_in, const int* in_sizes, int n_in,
                              void* d_out, int out_size) {
    const float* x   = (const float*)d_in[0];
    const float* Wq  = (const float*)d_in[1];
    const float* bq  = (const float*)d_in[2];
    const float* Wk  = (const float*)d_in[3];
    const float* bk  = (const float*)d_in[4];
    const float* Wv  = (const float*)d_in[5];
    const float* bv  = (const float*)d_in[6];
    const float* Wo  = (const float*)d_in[7];
    const float* bo  = (const float*)d_in[8];
    const float* pb  = (const float*)d_in[9];
    float* out = (float*)d_out;

    const int SMEM_GEMM = (64 * 128 + 128 * 128) * 4;                 // 96 KB
    const int SMEM_AFT  = (2 * JROWS * 128 + TI * WSZ) * 4;           // 178048 B

    static bool attr_done = false;
    if (!attr_done) {
        cudaFuncSetAttribute(k_qkv, cudaFuncAttributeMaxDynamicSharedMemorySize, SMEM_GEMM);
        cudaFuncSetAttribute(k_aft, cudaFuncAttributeMaxDynamicSharedMemorySize, SMEM_AFT);
        cudaFuncSetAttribute(k_out, cudaFuncAttributeMaxDynamicSharedMemorySize, SMEM_GEMM);
        attr_done = true;
    }

    k_window<<<L, 128>>>(pb);
    k_qkv<<<dim3(3, L / 64, NB), 256, SMEM_GEMM>>>(x, Wq, bq, Wk, bk, Wv, bv);
    k_sums<<<dim3(NB, 16), 128>>>();
    k_red<<<NB, 128>>>();
    k_aft<<<dim3(L / TI, NB), 256, SMEM_AFT>>>();
    k_out<<<dim3(L / 64, NB), 256, SMEM_GEMM>>>(Wo, bo, out);
}